// round 15
// baseline (speedup 1.0000x reference)
#include <cuda_runtime.h>
#include <cstdint>

#define BATCH 64
#define SEQ   1024
#define DIN   256
#define UNITS 512

__device__ __forceinline__ void fma2(unsigned long long& d, unsigned long long a,
                                     unsigned long long b) {
    asm("fma.rn.f32x2 %0, %1, %2, %0;" : "+l"(d) : "l"(a), "l"(b));
}
__device__ __forceinline__ unsigned long long pack2(float x, float y) {
    unsigned long long r;
    asm("mov.b64 %0, {%1, %2};" : "=l"(r) : "f"(x), "f"(y));
    return r;
}
__device__ __forceinline__ float sum2(unsigned long long p) {
    float lo, hi;
    asm("mov.b64 {%0, %1}, %2;" : "=f"(lo), "=f"(hi) : "l"(p));
    return lo + hi;
}

// ================= xW GEMM: C[65536,512] = X[65536,256] @ W[256,512] ==========
#define GM_TM 128
#define GM_TN 128
#define GM_TK 16

__global__ void __launch_bounds__(256) xw_gemm_kernel(const float* __restrict__ X,
                                                      const float* __restrict__ W,
                                                      float* __restrict__ C) {
    __shared__ float As[GM_TK][GM_TM + 4];
    __shared__ float Bs[GM_TK][GM_TN + 4];

    const int tid = threadIdx.x;
    const int bm = blockIdx.y * GM_TM;
    const int bn = blockIdx.x * GM_TN;
    const int tx = tid & 15;
    const int ty = tid >> 4;

    unsigned long long acc2[8][4];
#pragma unroll
    for (int i = 0; i < 8; i++)
#pragma unroll
        for (int j = 0; j < 4; j++) acc2[i][j] = 0ull;

    const int arow = tid >> 2;
    const int acol = (tid & 3) * 4;
    const int brow = tid >> 5;
    const int bcol = (tid & 31) * 4;

    for (int k0 = 0; k0 < DIN; k0 += GM_TK) {
#pragma unroll
        for (int p = 0; p < 2; p++) {
            float4 v = *(const float4*)&X[(size_t)(bm + arow + p * 64) * DIN + k0 + acol];
            As[acol + 0][arow + p * 64] = v.x;
            As[acol + 1][arow + p * 64] = v.y;
            As[acol + 2][arow + p * 64] = v.z;
            As[acol + 3][arow + p * 64] = v.w;
        }
#pragma unroll
        for (int p = 0; p < 2; p++) {
            *(float4*)&Bs[brow + p * 8][bcol] =
                *(const float4*)&W[(size_t)(k0 + brow + p * 8) * UNITS + bn + bcol];
        }
        __syncthreads();

#pragma unroll
        for (int kk = 0; kk < GM_TK; kk++) {
            float a[8];
            *(float4*)&a[0] = *(const float4*)&As[kk][ty * 8];
            *(float4*)&a[4] = *(const float4*)&As[kk][ty * 8 + 4];
            unsigned long long bp[4];
            *(ulonglong2*)&bp[0] = *(const ulonglong2*)&Bs[kk][tx * 8];
            *(ulonglong2*)&bp[2] = *(const ulonglong2*)&Bs[kk][tx * 8 + 4];
#pragma unroll
            for (int i = 0; i < 8; i++) {
                const unsigned long long av = pack2(a[i], a[i]);
                fma2(acc2[i][0], av, bp[0]);
                fma2(acc2[i][1], av, bp[1]);
                fma2(acc2[i][2], av, bp[2]);
                fma2(acc2[i][3], av, bp[3]);
            }
        }
        __syncthreads();
    }

#pragma unroll
    for (int i = 0; i < 8; i++) {
        size_t row = (size_t)(bm + ty * 8 + i) * UNITS + bn + tx * 8;
        ulonglong2 v0, v1;
        v0.x = acc2[i][0]; v0.y = acc2[i][1];
        v1.x = acc2[i][2]; v1.y = acc2[i][3];
        *(ulonglong2*)&C[row]     = v0;
        *(ulonglong2*)&C[row + 4] = v1;
    }
}

// ================= LTC scan: 2 interleaved streams per cluster ===============
// Cluster c owns batches [4c,4c+4): stream 0 = {4c,4c+1}, stream 1 = {4c+2,4c+3}.
// Rank s owns units [64s,64s+64). Warp w owns k-slice [64w,64w+64).
// While stream A's 512B DSMEM exchange is in flight, compute stream B.
#define CLUSTER_SZ 8
#define SCAN_CTAS 128
#define SLICE_BYTES 512                      // 2 batches * 64 units * 4B

__device__ __forceinline__ void cluster_sync_() {
    asm volatile("barrier.cluster.arrive.aligned;" ::: "memory");
    asm volatile("barrier.cluster.wait.aligned;"   ::: "memory");
}
__device__ __forceinline__ uint32_t mapa_u32(uint32_t addr, int rank) {
    uint32_t r;
    asm("mapa.shared::cluster.u32 %0, %1, %2;" : "=r"(r) : "r"(addr), "r"(rank));
    return r;
}
__device__ __forceinline__ void mbar_init(uint32_t mbar, uint32_t count) {
    asm volatile("mbarrier.init.shared.b64 [%0], %1;" :: "r"(mbar), "r"(count) : "memory");
}
__device__ __forceinline__ void mbar_expect_tx(uint32_t mbar, uint32_t bytes) {
    asm volatile("mbarrier.arrive.expect_tx.shared.b64 _, [%0], %1;"
                 :: "r"(mbar), "r"(bytes) : "memory");
}
__device__ __forceinline__ void mbar_wait(uint32_t mbar, uint32_t parity) {
    asm volatile(
        "{\n\t"
        ".reg .pred P1;\n\t"
        "WAIT_LOOP_%=:\n\t"
        "mbarrier.try_wait.parity.acquire.cta.shared::cta.b64 P1, [%0], %1, 0x989680;\n\t"
        "@P1 bra.uni WAIT_DONE_%=;\n\t"
        "bra.uni WAIT_LOOP_%=;\n\t"
        "WAIT_DONE_%=:\n\t"
        "}"
        :: "r"(mbar), "r"(parity) : "memory");
}
__device__ __forceinline__ void bulk_s2s(uint32_t dst_cluster, uint32_t src_cta,
                                         uint32_t bytes, uint32_t mbar_cluster) {
    asm volatile(
        "cp.async.bulk.shared::cluster.shared::cta.mbarrier::complete_tx::bytes "
        "[%0], [%1], %2, [%3];"
        :: "r"(dst_cluster), "r"(src_cta), "r"(bytes), "r"(mbar_cluster) : "memory");
}
__device__ __forceinline__ void fence_async_() {
    asm volatile("fence.proxy.async.shared::cta;" ::: "memory");
}

__global__ void __launch_bounds__(256, 1) __cluster_dims__(CLUSTER_SZ, 1, 1)
ltc_scan_kernel(const float* __restrict__ U,
                const float* __restrict__ bias,
                const float* __restrict__ tau,
                float* out) {
    // [stream][buf][slice][batch][u_local]; each slice block = 512B, contiguous
    __shared__ __align__(128) float hs[2][2][8][2][64];
    __shared__ float ps[2][8][2][68];        // [stream][warp][batch][u_local]
    __shared__ __align__(8) unsigned long long mbar[2][2][8];  // [stream][buf][slice]

    const int tid = threadIdx.x;
    const int w   = tid >> 5;               // warp -> k-slice
    const int l   = tid & 31;
    const int cta = blockIdx.x;
    const int s   = cta & 7;                // cluster rank = unit slice
    const int b0  = (cta >> 3) * 4;
    const int u0  = s * 64 + 2 * l;

    // ---- U slice in packed registers (shared by both streams) ----
    unsigned long long Urp0[32], Urp1[32];
#pragma unroll
    for (int p = 0; p < 32; p++) {
        const int k = w * 64 + 2 * p;
        float2 va = *(const float2*)&U[(size_t)k * UNITS + u0];
        float2 vb = *(const float2*)&U[(size_t)(k + 1) * UNITS + u0];
        Urp0[p] = pack2(va.x, vb.x);
        Urp1[p] = pack2(va.y, vb.y);
    }

    // ---- epilogue mapping: threads 0..127 -> (eb in 0..1, eul in 0..63) ----
    const int eb  = (tid >> 6) & 1;          // batch within stream
    const int eul = tid & 63;
    const int eu  = s * 64 + eul;
    const float invt = 1.0f / tau[eu];
    const float aa   = 1.0f - invt;
    const float bi   = bias[eu];
    float* orowA = out + (size_t)(b0 + eb)     * SEQ * UNITS + eu;   // stream 0
    float* orowB = out + (size_t)(b0 + 2 + eb) * SEQ * UNITS + eu;   // stream 1

    // ---- zero buf0 of both streams ----
    for (int i = tid; i < 2 * 8 * 2 * 64; i += 256) {
        ((float*)hs[0][0])[i & 1023] = 0.0f;       // stream0 buf0
        ((float*)hs[1][0])[i & 1023] = 0.0f;       // stream1 buf0
    }

    const uint32_t mbar_base = (uint32_t)__cvta_generic_to_shared(&mbar[0][0][0]);
    // own-slice source addresses: [stream][buf]
    uint32_t src_addr[2][2];
#pragma unroll
    for (int sg = 0; sg < 2; sg++)
#pragma unroll
        for (int bf = 0; bf < 2; bf++)
            src_addr[sg][bf] = (uint32_t)__cvta_generic_to_shared(&hs[sg][bf][s][0][0]);

    if (tid < 32) {                          // (stream=tid>>4, buf=(tid>>3)&1, slice=tid&7)
        const int sl = tid & 7;
        if (sl != s) {
            const uint32_t mb = mbar_base + (uint32_t)tid * 8;
            mbar_init(mb, 1);
            mbar_expect_tx(mb, SLICE_BYTES);
        }
    }
    __syncthreads();
    cluster_sync_();                         // mbars + h0 visible cluster-wide

    const bool epi = (tid < 128);
    float xwA = epi ? __ldg(orowA) : 0.0f;
    float xwB = epi ? __ldg(orowB) : 0.0f;
    int phA0 = 0, phA1 = 0, phB0 = 0, phB1 = 0;

    // mbar address for (stream sg, buf bf, slice w):
    #define MB(sg, bf) (mbar_base + (uint32_t)((((sg) * 2 + (bf)) * 8) + w) * 8)
    #define MBS(sg, bf) (mbar_base + (uint32_t)((((sg) * 2 + (bf)) * 8) + s) * 8)

    for (int t = 0; t < SEQ; t++) {
        const int cur = t & 1;
        const int nb  = cur ^ 1;

        // ==================== PHASE macro: one stream step ====================
        #define PHASE(SG, PH0, PH1, XW, OROW)                                          \
        {                                                                              \
            if (t > 0 && w != s) {                                                     \
                const uint32_t mb = cur ? MB(SG, 1) : MB(SG, 0);                       \
                mbar_wait(mb, (uint32_t)(cur ? PH1 : PH0));                            \
                if (l == 0) mbar_expect_tx(mb, SLICE_BYTES);                           \
            }                                                                          \
            if (t > 0) { if (cur) PH1 ^= 1; else PH0 ^= 1; }                           \
            unsigned long long a00 = 0ull, a01 = 0ull, a10 = 0ull, a11 = 0ull;         \
            _Pragma("unroll")                                                          \
            for (int j = 0; j < 16; j++) {                                             \
                ulonglong2 h0 = *(const ulonglong2*)&hs[SG][cur][w][0][j * 4];         \
                ulonglong2 h1 = *(const ulonglong2*)&hs[SG][cur][w][1][j * 4];         \
                fma2(a00, h0.x, Urp0[2 * j]);  fma2(a00, h0.y, Urp0[2 * j + 1]);       \
                fma2(a01, h0.x, Urp1[2 * j]);  fma2(a01, h0.y, Urp1[2 * j + 1]);       \
                fma2(a10, h1.x, Urp0[2 * j]);  fma2(a10, h1.y, Urp0[2 * j + 1]);       \
                fma2(a11, h1.x, Urp1[2 * j]);  fma2(a11, h1.y, Urp1[2 * j + 1]);       \
            }                                                                          \
            *(float2*)&ps[SG][w][0][2 * l] = make_float2(sum2(a00), sum2(a01));        \
            *(float2*)&ps[SG][w][1][2 * l] = make_float2(sum2(a10), sum2(a11));        \
            __syncthreads();                                                           \
            float hn = 0.0f;                                                           \
            if (epi) {                                                                 \
                float r = 0.0f;                                                        \
                _Pragma("unroll")                                                      \
                for (int w2 = 0; w2 < 8; w2++) r += ps[SG][w2][eb][eul];               \
                const float hold = hs[SG][cur][s][eb][eul];                            \
                hn = fmaf(aa, hold, invt * (r + XW + bi));                             \
                if (t + 1 < SEQ) hs[SG][nb][s][eb][eul] = hn;                          \
            }                                                                          \
            __syncthreads();                                                           \
            if (t + 1 < SEQ && tid < 8 && tid != s) {                                  \
                fence_async_();                                                        \
                const uint32_t src = src_addr[SG][nb];                                 \
                const uint32_t dst = mapa_u32(src, tid);                               \
                const uint32_t mb  = mapa_u32(MBS(SG, nb), tid);                       \
                bulk_s2s(dst, src, SLICE_BYTES, mb);                                   \
            }                                                                          \
            if (epi) {                                                                 \
                OROW[(size_t)t * UNITS] = hn;                                          \
                if (t + 1 < SEQ) XW = __ldg(OROW + (size_t)(t + 1) * UNITS);           \
            }                                                                          \
        }
        // ======================================================================

        PHASE(0, phA0, phA1, xwA, orowA)     // stream A
        PHASE(1, phB0, phB1, xwB, orowB)     // stream B (covers A's exchange)

        #undef PHASE
    }
    #undef MB
    #undef MBS

    cluster_sync_();                         // no CTA exits with peers' DMAs pending
}

// =============================== launch ======================================
extern "C" void kernel_launch(void* const* d_in, const int* in_sizes, int n_in,
                              void* d_out, int out_size) {
    const float* x    = (const float*)d_in[0];   // [64,1024,256]
    const float* W    = (const float*)d_in[1];   // [256,512]
    const float* U    = (const float*)d_in[2];   // [512,512]
    const float* bias = (const float*)d_in[3];   // [512]
    const float* tau  = (const float*)d_in[4];   // [512]
    float* out = (float*)d_out;                  // [64,1024,512]

    dim3 ggrid(UNITS / GM_TN, (BATCH * SEQ) / GM_TM);   // (4, 512)
    xw_gemm_kernel<<<ggrid, 256>>>(x, W, out);

    ltc_scan_kernel<<<SCAN_CTAS, 256>>>(U, bias, tau, out);
}

// round 16
// speedup vs baseline: 1.0071x; 1.0071x over previous
#include <cuda_runtime.h>
#include <cstdint>

#define BATCH 64
#define SEQ   1024
#define DIN   256
#define UNITS 512

__device__ __forceinline__ void fma2(unsigned long long& d, unsigned long long a,
                                     unsigned long long b) {
    asm("fma.rn.f32x2 %0, %1, %2, %0;" : "+l"(d) : "l"(a), "l"(b));
}
__device__ __forceinline__ unsigned long long pack2(float x, float y) {
    unsigned long long r;
    asm("mov.b64 %0, {%1, %2};" : "=l"(r) : "f"(x), "f"(y));
    return r;
}
__device__ __forceinline__ float sum2(unsigned long long p) {
    float lo, hi;
    asm("mov.b64 {%0, %1}, %2;" : "=f"(lo), "=f"(hi) : "l"(p));
    return lo + hi;
}

// ================= xW GEMM: C[65536,512] = X[65536,256] @ W[256,512] ==========
#define GM_TM 128
#define GM_TN 128
#define GM_TK 16

__global__ void __launch_bounds__(256) xw_gemm_kernel(const float* __restrict__ X,
                                                      const float* __restrict__ W,
                                                      float* __restrict__ C) {
    __shared__ float As[GM_TK][GM_TM + 4];
    __shared__ float Bs[GM_TK][GM_TN + 4];

    const int tid = threadIdx.x;
    const int bm = blockIdx.y * GM_TM;
    const int bn = blockIdx.x * GM_TN;
    const int tx = tid & 15;
    const int ty = tid >> 4;

    unsigned long long acc2[8][4];
#pragma unroll
    for (int i = 0; i < 8; i++)
#pragma unroll
        for (int j = 0; j < 4; j++) acc2[i][j] = 0ull;

    const int arow = tid >> 2;
    const int acol = (tid & 3) * 4;
    const int brow = tid >> 5;
    const int bcol = (tid & 31) * 4;

    for (int k0 = 0; k0 < DIN; k0 += GM_TK) {
#pragma unroll
        for (int p = 0; p < 2; p++) {
            float4 v = *(const float4*)&X[(size_t)(bm + arow + p * 64) * DIN + k0 + acol];
            As[acol + 0][arow + p * 64] = v.x;
            As[acol + 1][arow + p * 64] = v.y;
            As[acol + 2][arow + p * 64] = v.z;
            As[acol + 3][arow + p * 64] = v.w;
        }
#pragma unroll
        for (int p = 0; p < 2; p++) {
            *(float4*)&Bs[brow + p * 8][bcol] =
                *(const float4*)&W[(size_t)(k0 + brow + p * 8) * UNITS + bn + bcol];
        }
        __syncthreads();

#pragma unroll
        for (int kk = 0; kk < GM_TK; kk++) {
            float a[8];
            *(float4*)&a[0] = *(const float4*)&As[kk][ty * 8];
            *(float4*)&a[4] = *(const float4*)&As[kk][ty * 8 + 4];
            unsigned long long bp[4];
            *(ulonglong2*)&bp[0] = *(const ulonglong2*)&Bs[kk][tx * 8];
            *(ulonglong2*)&bp[2] = *(const ulonglong2*)&Bs[kk][tx * 8 + 4];
#pragma unroll
            for (int i = 0; i < 8; i++) {
                const unsigned long long av = pack2(a[i], a[i]);
                fma2(acc2[i][0], av, bp[0]);
                fma2(acc2[i][1], av, bp[1]);
                fma2(acc2[i][2], av, bp[2]);
                fma2(acc2[i][3], av, bp[3]);
            }
        }
        __syncthreads();
    }

#pragma unroll
    for (int i = 0; i < 8; i++) {
        size_t row = (size_t)(bm + ty * 8 + i) * UNITS + bn + tx * 8;
        ulonglong2 v0, v1;
        v0.x = acc2[i][0]; v0.y = acc2[i][1];
        v1.x = acc2[i][2]; v1.y = acc2[i][3];
        *(ulonglong2*)&C[row]     = v0;
        *(ulonglong2*)&C[row + 4] = v1;
    }
}

// ================= LTC scan: 2 interleaved streams per cluster ===============
// Cluster c owns batches [4c,4c+4): stream 0 = {4c,4c+1}, stream 1 = {4c+2,4c+3}.
// Rank s owns units [64s,64s+64). Warp w owns k-slice [64w,64w+64).
// While stream A's 512B DSMEM exchange is in flight, compute stream B.
#define CLUSTER_SZ 8
#define SCAN_CTAS 128
#define SLICE_BYTES 512                      // 2 batches * 64 units * 4B

__device__ __forceinline__ void cluster_sync_() {
    asm volatile("barrier.cluster.arrive.aligned;" ::: "memory");
    asm volatile("barrier.cluster.wait.aligned;"   ::: "memory");
}
__device__ __forceinline__ uint32_t mapa_u32(uint32_t addr, int rank) {
    uint32_t r;
    asm("mapa.shared::cluster.u32 %0, %1, %2;" : "=r"(r) : "r"(addr), "r"(rank));
    return r;
}
__device__ __forceinline__ void mbar_init(uint32_t mbar, uint32_t count) {
    asm volatile("mbarrier.init.shared.b64 [%0], %1;" :: "r"(mbar), "r"(count) : "memory");
}
__device__ __forceinline__ void mbar_expect_tx(uint32_t mbar, uint32_t bytes) {
    asm volatile("mbarrier.arrive.expect_tx.shared.b64 _, [%0], %1;"
                 :: "r"(mbar), "r"(bytes) : "memory");
}
__device__ __forceinline__ void mbar_wait(uint32_t mbar, uint32_t parity) {
    asm volatile(
        "{\n\t"
        ".reg .pred P1;\n\t"
        "WAIT_LOOP_%=:\n\t"
        "mbarrier.try_wait.parity.acquire.cta.shared::cta.b64 P1, [%0], %1, 0x989680;\n\t"
        "@P1 bra.uni WAIT_DONE_%=;\n\t"
        "bra.uni WAIT_LOOP_%=;\n\t"
        "WAIT_DONE_%=:\n\t"
        "}"
        :: "r"(mbar), "r"(parity) : "memory");
}
__device__ __forceinline__ void bulk_s2s(uint32_t dst_cluster, uint32_t src_cta,
                                         uint32_t bytes, uint32_t mbar_cluster) {
    asm volatile(
        "cp.async.bulk.shared::cluster.shared::cta.mbarrier::complete_tx::bytes "
        "[%0], [%1], %2, [%3];"
        :: "r"(dst_cluster), "r"(src_cta), "r"(bytes), "r"(mbar_cluster) : "memory");
}
__device__ __forceinline__ void fence_async_() {
    asm volatile("fence.proxy.async.shared::cta;" ::: "memory");
}

__global__ void __launch_bounds__(256, 1) __cluster_dims__(CLUSTER_SZ, 1, 1)
ltc_scan_kernel(const float* __restrict__ U,
                const float* __restrict__ bias,
                const float* __restrict__ tau,
                float* out) {
    // [stream][buf][slice][batch][u_local]; each slice block = 512B, contiguous
    __shared__ __align__(128) float hs[2][2][8][2][64];
    __shared__ float ps[2][8][2][68];        // [stream][warp][batch][u_local]
    __shared__ __align__(8) unsigned long long mbar[2][2][8];  // [stream][buf][slice]

    const int tid = threadIdx.x;
    const int w   = tid >> 5;               // warp -> k-slice
    const int l   = tid & 31;
    const int cta = blockIdx.x;
    const int s   = cta & 7;                // cluster rank = unit slice
    const int b0  = (cta >> 3) * 4;
    const int u0  = s * 64 + 2 * l;

    // ---- U slice in packed registers (shared by both streams) ----
    unsigned long long Urp0[32], Urp1[32];
#pragma unroll
    for (int p = 0; p < 32; p++) {
        const int k = w * 64 + 2 * p;
        float2 va = *(const float2*)&U[(size_t)k * UNITS + u0];
        float2 vb = *(const float2*)&U[(size_t)(k + 1) * UNITS + u0];
        Urp0[p] = pack2(va.x, vb.x);
        Urp1[p] = pack2(va.y, vb.y);
    }

    // ---- epilogue mapping: threads 0..127 -> (eb in 0..1, eul in 0..63) ----
    const int eb  = (tid >> 6) & 1;          // batch within stream
    const int eul = tid & 63;
    const int eu  = s * 64 + eul;
    const float invt = 1.0f / tau[eu];
    const float aa   = 1.0f - invt;
    const float bi   = bias[eu];
    float* orowA = out + (size_t)(b0 + eb)     * SEQ * UNITS + eu;   // stream 0
    float* orowB = out + (size_t)(b0 + 2 + eb) * SEQ * UNITS + eu;   // stream 1

    // ---- zero buf0 of both streams ----
    for (int i = tid; i < 2 * 8 * 2 * 64; i += 256) {
        ((float*)hs[0][0])[i & 1023] = 0.0f;       // stream0 buf0
        ((float*)hs[1][0])[i & 1023] = 0.0f;       // stream1 buf0
    }

    const uint32_t mbar_base = (uint32_t)__cvta_generic_to_shared(&mbar[0][0][0]);
    // own-slice source addresses: [stream][buf]
    uint32_t src_addr[2][2];
#pragma unroll
    for (int sg = 0; sg < 2; sg++)
#pragma unroll
        for (int bf = 0; bf < 2; bf++)
            src_addr[sg][bf] = (uint32_t)__cvta_generic_to_shared(&hs[sg][bf][s][0][0]);

    if (tid < 32) {                          // (stream=tid>>4, buf=(tid>>3)&1, slice=tid&7)
        const int sl = tid & 7;
        if (sl != s) {
            const uint32_t mb = mbar_base + (uint32_t)tid * 8;
            mbar_init(mb, 1);
            mbar_expect_tx(mb, SLICE_BYTES);
        }
    }
    __syncthreads();
    cluster_sync_();                         // mbars + h0 visible cluster-wide

    const bool epi = (tid < 128);
    float xwA = epi ? __ldg(orowA) : 0.0f;
    float xwB = epi ? __ldg(orowB) : 0.0f;
    int phA0 = 0, phA1 = 0, phB0 = 0, phB1 = 0;

    // mbar address for (stream sg, buf bf, slice w):
    #define MB(sg, bf) (mbar_base + (uint32_t)((((sg) * 2 + (bf)) * 8) + w) * 8)
    #define MBS(sg, bf) (mbar_base + (uint32_t)((((sg) * 2 + (bf)) * 8) + s) * 8)

    for (int t = 0; t < SEQ; t++) {
        const int cur = t & 1;
        const int nb  = cur ^ 1;

        // ==================== PHASE macro: one stream step ====================
        #define PHASE(SG, PH0, PH1, XW, OROW)                                          \
        {                                                                              \
            if (t > 0 && w != s) {                                                     \
                const uint32_t mb = cur ? MB(SG, 1) : MB(SG, 0);                       \
                mbar_wait(mb, (uint32_t)(cur ? PH1 : PH0));                            \
                if (l == 0) mbar_expect_tx(mb, SLICE_BYTES);                           \
            }                                                                          \
            if (t > 0) { if (cur) PH1 ^= 1; else PH0 ^= 1; }                           \
            unsigned long long a00 = 0ull, a01 = 0ull, a10 = 0ull, a11 = 0ull;         \
            _Pragma("unroll")                                                          \
            for (int j = 0; j < 16; j++) {                                             \
                ulonglong2 h0 = *(const ulonglong2*)&hs[SG][cur][w][0][j * 4];         \
                ulonglong2 h1 = *(const ulonglong2*)&hs[SG][cur][w][1][j * 4];         \
                fma2(a00, h0.x, Urp0[2 * j]);  fma2(a00, h0.y, Urp0[2 * j + 1]);       \
                fma2(a01, h0.x, Urp1[2 * j]);  fma2(a01, h0.y, Urp1[2 * j + 1]);       \
                fma2(a10, h1.x, Urp0[2 * j]);  fma2(a10, h1.y, Urp0[2 * j + 1]);       \
                fma2(a11, h1.x, Urp1[2 * j]);  fma2(a11, h1.y, Urp1[2 * j + 1]);       \
            }                                                                          \
            *(float2*)&ps[SG][w][0][2 * l] = make_float2(sum2(a00), sum2(a01));        \
            *(float2*)&ps[SG][w][1][2 * l] = make_float2(sum2(a10), sum2(a11));        \
            __syncthreads();                                                           \
            float hn = 0.0f;                                                           \
            if (epi) {                                                                 \
                float r = 0.0f;                                                        \
                _Pragma("unroll")                                                      \
                for (int w2 = 0; w2 < 8; w2++) r += ps[SG][w2][eb][eul];               \
                const float hold = hs[SG][cur][s][eb][eul];                            \
                hn = fmaf(aa, hold, invt * (r + XW + bi));                             \
                if (t + 1 < SEQ) hs[SG][nb][s][eb][eul] = hn;                          \
            }                                                                          \
            __syncthreads();                                                           \
            if (t + 1 < SEQ && tid < 8 && tid != s) {                                  \
                fence_async_();                                                        \
                const uint32_t src = src_addr[SG][nb];                                 \
                const uint32_t dst = mapa_u32(src, tid);                               \
                const uint32_t mb  = mapa_u32(MBS(SG, nb), tid);                       \
                bulk_s2s(dst, src, SLICE_BYTES, mb);                                   \
            }                                                                          \
            if (epi) {                                                                 \
                OROW[(size_t)t * UNITS] = hn;                                          \
                if (t + 1 < SEQ) XW = __ldg(OROW + (size_t)(t + 1) * UNITS);           \
            }                                                                          \
        }
        // ======================================================================

        PHASE(0, phA0, phA1, xwA, orowA)     // stream A
        PHASE(1, phB0, phB1, xwB, orowB)     // stream B (covers A's exchange)

        #undef PHASE
    }
    #undef MB
    #undef MBS

    cluster_sync_();                         // no CTA exits with peers' DMAs pending
}

// =============================== launch ======================================
extern "C" void kernel_launch(void* const* d_in, const int* in_sizes, int n_in,
                              void* d_out, int out_size) {
    const float* x    = (const float*)d_in[0];   // [64,1024,256]
    const float* W    = (const float*)d_in[1];   // [256,512]
    const float* U    = (const float*)d_in[2];   // [512,512]
    const float* bias = (const float*)d_in[3];   // [512]
    const float* tau  = (const float*)d_in[4];   // [512]
    float* out = (float*)d_out;                  // [64,1024,512]

    dim3 ggrid(UNITS / GM_TN, (BATCH * SEQ) / GM_TM);   // (4, 512)
    xw_gemm_kernel<<<ggrid, 256>>>(x, W, out);

    ltc_scan_kernel<<<SCAN_CTAS, 256>>>(U, bias, tau, out);
}